// round 4
// baseline (speedup 1.0000x reference)
#include <cuda_runtime.h>
#include <math.h>

// ---------------------------------------------------------------------------
// Problem constants
//  B=4, S=1024, D=1024, NH=16, NKV=4, HD=64, BLK_SIZE=8, HIDDEN=1024
//  mod rows = B*128 = 512, mod cols = 3072
// ---------------------------------------------------------------------------

#define TOT_ROWS 4096           // B*S
#define DIMC     1024
#define KVDIM    256
#define MODM     512            // B*BLK_NUM
#define MODN     3072

// ---------------- scratch (device globals; no allocations) -----------------
__device__ float g_sv  [MODM * DIMC];        // silu(vec)
__device__ float g_moda[MODM * MODN];        // attn modulation (shift|scale|gate)
__device__ float g_modf[MODM * MODN];        // ffn  modulation
__device__ float g_xn  [TOT_ROWS * DIMC];
__device__ float g_q   [TOT_ROWS * DIMC];
__device__ float g_k   [TOT_ROWS * KVDIM];
__device__ float g_v   [TOT_ROWS * KVDIM];
__device__ float g_att [TOT_ROWS * DIMC];
__device__ float g_h   [TOT_ROWS * DIMC];
__device__ float g_hn  [TOT_ROWS * DIMC];
__device__ float g_u   [TOT_ROWS * DIMC];
__device__ float g_g   [TOT_ROWS * DIMC];
__device__ float g_f   [TOT_ROWS * DIMC];

// ---------------------------------------------------------------------------
// SGEMM: C[M,N] = A[M,K] * B[N,K]^T  (both row-major; B is a weight [N,K])
//   MODE 0: C = A B^T
//   MODE 1: C = A B^T + bias[n]                      (aux1 = bias)
//   MODE 2: C = resid + gate * (A B^T)               (aux1 = resid [M,N],
//            gate[n] = aux2[modrow*3072 + 2048 + n],  aux2 = mod buffer)
// Tiles: BM=BN=128, BK=8, 256 threads, 8x8 microtile per thread.
// Requires M%128==0, N%128==0, K%8==0 (true for every call here).
// ---------------------------------------------------------------------------
template <int MODE>
__global__ __launch_bounds__(256, 2)
void sgemm_k(const float* __restrict__ A, const float* __restrict__ B,
             float* __restrict__ C, int M, int N, int K,
             const float* __restrict__ aux1, const float* __restrict__ aux2)
{
    __shared__ float As[8][128];
    __shared__ float Bs[8][128];

    const int bm  = blockIdx.y * 128;
    const int bn  = blockIdx.x * 128;
    const int tid = threadIdx.x;
    const int lrow = tid >> 1;          // 0..127
    const int lcol = (tid & 1) << 2;    // 0 or 4
    const int ty = tid >> 4;            // 0..15
    const int tx = tid & 15;            // 0..15

    float acc[8][8];
#pragma unroll
    for (int i = 0; i < 8; i++)
#pragma unroll
        for (int j = 0; j < 8; j++) acc[i][j] = 0.f;

    const float* Ap = A + (size_t)(bm + lrow) * K + lcol;
    const float* Bp = B + (size_t)(bn + lrow) * K + lcol;

    for (int k0 = 0; k0 < K; k0 += 8) {
        float4 a4 = *(const float4*)(Ap + k0);
        float4 b4 = *(const float4*)(Bp + k0);
        As[lcol + 0][lrow] = a4.x; As[lcol + 1][lrow] = a4.y;
        As[lcol + 2][lrow] = a4.z; As[lcol + 3][lrow] = a4.w;
        Bs[lcol + 0][lrow] = b4.x; Bs[lcol + 1][lrow] = b4.y;
        Bs[lcol + 2][lrow] = b4.z; Bs[lcol + 3][lrow] = b4.w;
        __syncthreads();
#pragma unroll
        for (int kk = 0; kk < 8; kk++) {
            float ar[8], br[8];
#pragma unroll
            for (int i = 0; i < 8; i++) ar[i] = As[kk][ty * 8 + i];
#pragma unroll
            for (int j = 0; j < 8; j++) br[j] = Bs[kk][tx * 8 + j];
#pragma unroll
            for (int i = 0; i < 8; i++)
#pragma unroll
                for (int j = 0; j < 8; j++) acc[i][j] += ar[i] * br[j];
        }
        __syncthreads();
    }

#pragma unroll
    for (int i = 0; i < 8; i++) {
        const int row  = bm + ty * 8 + i;
        const int col0 = bn + tx * 8;
        float* cp = C + (size_t)row * N + col0;
        if (MODE == 0) {
#pragma unroll
            for (int j = 0; j < 8; j++) cp[j] = acc[i][j];
        } else if (MODE == 1) {
            const float* bi = aux1 + col0;
#pragma unroll
            for (int j = 0; j < 8; j++) cp[j] = acc[i][j] + bi[j];
        } else {
            const int modrow = ((row >> 10) << 7) + ((row & 1023) >> 3);
            const float* gp = aux2 + (size_t)modrow * MODN + 2048 + col0;
            const float* rp = aux1 + (size_t)row * N + col0;
#pragma unroll
            for (int j = 0; j < 8; j++) cp[j] = rp[j] + gp[j] * acc[i][j];
        }
    }
}

// ---------------------------------------------------------------------------
// silu elementwise
// ---------------------------------------------------------------------------
__global__ void silu_k(const float* __restrict__ in, float* __restrict__ out, int n)
{
    int i = blockIdx.x * blockDim.x + threadIdx.x;
    if (i < n) {
        float v = in[i];
        out[i] = v / (1.f + __expf(-v));
    }
}

// silu(u) * g
__global__ void silumul_k(const float* __restrict__ u, const float* __restrict__ g,
                          float* __restrict__ f, int n)
{
    int i = blockIdx.x * blockDim.x + threadIdx.x;
    if (i < n) {
        float v = u[i];
        f[i] = (v / (1.f + __expf(-v))) * g[i];
    }
}

// ---------------------------------------------------------------------------
// Fused rmsnorm + adaLN modulation:  Y = rmsnorm(X,w) * (1+scale) + shift
// one block per row (1024 cols), 256 threads (4 cols each, float4)
// ---------------------------------------------------------------------------
__global__ __launch_bounds__(256)
void rmsnorm_mod_k(const float* __restrict__ X, const float* __restrict__ w,
                   const float* __restrict__ mod, float* __restrict__ Y)
{
    const int row = blockIdx.x;
    const int modrow = ((row >> 10) << 7) + ((row & 1023) >> 3);
    const float* x  = X + (size_t)row * DIMC;
    const float* sh = mod + (size_t)modrow * MODN;
    const float* sc = sh + 1024;
    const int t = threadIdx.x;

    float4 xv = *(const float4*)(x + t * 4);
    float ss = xv.x * xv.x + xv.y * xv.y + xv.z * xv.z + xv.w * xv.w;
#pragma unroll
    for (int o = 16; o > 0; o >>= 1) ss += __shfl_xor_sync(0xffffffffu, ss, o);

    __shared__ float red[8];
    if ((t & 31) == 0) red[t >> 5] = ss;
    __syncthreads();
    float tot = 0.f;
#pragma unroll
    for (int i = 0; i < 8; i++) tot += red[i];

    float rinv = rsqrtf(tot * (1.f / 1024.f) + 1e-6f);
    float4 wv = *(const float4*)(w + t * 4);
    float4 scv = *(const float4*)(sc + t * 4);
    float4 shv = *(const float4*)(sh + t * 4);
    float4 yv;
    yv.x = xv.x * rinv * wv.x * (1.f + scv.x) + shv.x;
    yv.y = xv.y * rinv * wv.y * (1.f + scv.y) + shv.y;
    yv.z = xv.z * rinv * wv.z * (1.f + scv.z) + shv.z;
    yv.w = xv.w * rinv * wv.w * (1.f + scv.w) + shv.w;
    *(float4*)(Y + (size_t)row * DIMC + t * 4) = yv;
}

// ---------------------------------------------------------------------------
// RoPE in-place on q (4096x1024, 16 heads) and k (4096x256, 4 heads)
// one thread per (row, pair)
// ---------------------------------------------------------------------------
__global__ void rope_k(float* __restrict__ q, float* __restrict__ k,
                       const float* __restrict__ fc, const float* __restrict__ fs)
{
    const int nq = TOT_ROWS * 512;          // pairs in q
    int idx = blockIdx.x * blockDim.x + threadIdx.x;
    if (idx < nq) {
        int row = idx >> 9;
        int p = idx & 511;
        int head = p >> 5, i = p & 31;
        int s = row & 1023;
        float c = fc[s * 32 + i], sn = fs[s * 32 + i];
        float* base = q + (size_t)row * DIMC + head * 64 + i * 2;
        float x1 = base[0], x2 = base[1];
        base[0] = x1 * c - x2 * sn;
        base[1] = x1 * sn + x2 * c;
    } else {
        int j = idx - nq;                   // pairs in k: 4096*128
        int row = j >> 7;
        int p = j & 127;
        int head = p >> 5, i = p & 31;
        int s = row & 1023;
        float c = fc[s * 32 + i], sn = fs[s * 32 + i];
        float* base = k + (size_t)row * KVDIM + head * 64 + i * 2;
        float x1 = base[0], x2 = base[1];
        base[0] = x1 * c - x2 * sn;
        base[1] = x1 * sn + x2 * c;
    }
}

// ---------------------------------------------------------------------------
// Block-causal flash attention.
// grid (qtile 0..7, head 0..15, batch 0..3), 128 threads, 1 thread = 1 query.
// Q row + O accumulator in registers; K/V 32-row chunks in smem.
// key limit for query r: keys kg with kg/8 <= r/8  <=>  kg < r - r%8 + 8.
// ---------------------------------------------------------------------------
__global__ __launch_bounds__(128, 2)
void attn_k(const float* __restrict__ Q, const float* __restrict__ K,
            const float* __restrict__ V, float* __restrict__ O)
{
    const int qt = blockIdx.x, h = blockIdx.y, b = blockIdx.z;
    const int kvh = h >> 2;
    const int q0 = qt * 128;
    const int r = q0 + threadIdx.x;
    const int grow = b * 1024 + r;

    __shared__ float ks[32][64];
    __shared__ float vs[32][64];

    float4 qf[16], of[16];
    const float4* qp = (const float4*)(Q + (size_t)grow * DIMC + h * 64);
#pragma unroll
    for (int i = 0; i < 16; i++) { qf[i] = qp[i]; of[i] = make_float4(0.f, 0.f, 0.f, 0.f); }

    float m = -1e30f, l = 0.f;
    const int lim = r - (r & 7) + 8;      // exclusive key limit for this row
    const int kend = q0 + 128;            // max key any row in this tile can see
    const float scale = 0.125f;           // 1/sqrt(64)

    const int jr = threadIdx.x >> 2;          // load row 0..31
    const int jc = (threadIdx.x & 3) * 16;    // load col base

    for (int kc = 0; kc < kend; kc += 32) {
        const float4* kp = (const float4*)(K + (size_t)(b * 1024 + kc + jr) * KVDIM + kvh * 64 + jc);
        const float4* vp = (const float4*)(V + (size_t)(b * 1024 + kc + jr) * KVDIM + kvh * 64 + jc);
        float4* ksd = (float4*)&ks[jr][jc];
        float4* vsd = (float4*)&vs[jr][jc];
#pragma unroll
        for (int uu = 0; uu < 4; uu++) { ksd[uu] = kp[uu]; vsd[uu] = vp[uu]; }
        __syncthreads();

        float sc[32];
#pragma unroll
        for (int j = 0; j < 32; j++) {
            const float4* kr = (const float4*)ks[j];
            float s = 0.f;
#pragma unroll
            for (int d = 0; d < 16; d++) {
                float4 kv4 = kr[d];
                s += qf[d].x * kv4.x + qf[d].y * kv4.y + qf[d].z * kv4.z + qf[d].w * kv4.w;
            }
            int kg = kc + j;
            sc[j] = (kg < lim) ? s * scale : -1e30f;
        }

        float mnew = m;
#pragma unroll
        for (int j = 0; j < 32; j++) mnew = fmaxf(mnew, sc[j]);
        float corr = __expf(m - mnew);
        l *= corr;
#pragma unroll
        for (int i = 0; i < 16; i++) {
            of[i].x *= corr; of[i].y *= corr; of[i].z *= corr; of[i].w *= corr;
        }
#pragma unroll
        for (int j = 0; j < 32; j++) {
            float p = __expf(sc[j] - mnew);
            l += p;
            const float4* vr = (const float4*)vs[j];
#pragma unroll
            for (int d = 0; d < 16; d++) {
                float4 vv = vr[d];
                of[d].x += p * vv.x; of[d].y += p * vv.y;
                of[d].z += p * vv.z; of[d].w += p * vv.w;
            }
        }
        m = mnew;
        __syncthreads();
    }

    float inv = 1.f / l;
    float4* op = (float4*)(O + (size_t)grow * DIMC + h * 64);
#pragma unroll
    for (int i = 0; i < 16; i++) {
        float4 o4;
        o4.x = of[i].x * inv; o4.y = of[i].y * inv;
        o4.z = of[i].z * inv; o4.w = of[i].w * inv;
        op[i] = o4;
    }
}

// ---------------------------------------------------------------------------
// Launcher
// ---------------------------------------------------------------------------
extern "C" void kernel_launch(void* const* d_in, const int* in_sizes, int n_in,
                              void* d_out, int out_size)
{
    (void)in_sizes; (void)n_in; (void)out_size;
    const float* x   = (const float*)d_in[0];
    const float* vec = (const float*)d_in[1];
    const float* wq  = (const float*)d_in[2];
    const float* wk  = (const float*)d_in[3];
    const float* wv  = (const float*)d_in[4];
    const float* wo  = (const float*)d_in[5];
    const float* w1  = (const float*)d_in[6];
    const float* w2  = (const float*)d_in[7];
    const float* w3  = (const float*)d_in[8];
    const float* maw = (const float*)d_in[9];
    const float* mab = (const float*)d_in[10];
    const float* mfw = (const float*)d_in[11];
    const float* mfb = (const float*)d_in[12];
    const float* n1w = (const float*)d_in[13];
    const float* n2w = (const float*)d_in[14];
    const float* fc  = (const float*)d_in[15];
    const float* fs  = (const float*)d_in[16];
    float* out = (float*)d_out;

    float *sv, *moda, *modf, *xn, *q, *k, *v, *att, *h, *hn, *u, *g, *f;
    cudaGetSymbolAddress((void**)&sv,   g_sv);
    cudaGetSymbolAddress((void**)&moda, g_moda);
    cudaGetSymbolAddress((void**)&modf, g_modf);
    cudaGetSymbolAddress((void**)&xn,   g_xn);
    cudaGetSymbolAddress((void**)&q,    g_q);
    cudaGetSymbolAddress((void**)&k,    g_k);
    cudaGetSymbolAddress((void**)&v,    g_v);
    cudaGetSymbolAddress((void**)&att,  g_att);
    cudaGetSymbolAddress((void**)&h,    g_h);
    cudaGetSymbolAddress((void**)&hn,   g_hn);
    cudaGetSymbolAddress((void**)&u,    g_u);
    cudaGetSymbolAddress((void**)&g,    g_g);
    cudaGetSymbolAddress((void**)&f,    g_f);

    // 1) modulation: silu(vec) then two (512,3072,1024) GEMMs with bias
    silu_k<<<(MODM * DIMC) / 256, 256>>>(vec, sv, MODM * DIMC);
    sgemm_k<1><<<dim3(MODN / 128, MODM / 128), 256>>>(sv, maw, moda, MODM, MODN, DIMC, mab, nullptr);
    sgemm_k<1><<<dim3(MODN / 128, MODM / 128), 256>>>(sv, mfw, modf, MODM, MODN, DIMC, mfb, nullptr);

    // 2) xn = rmsnorm(x)* (1+scale_a) + shift_a
    rmsnorm_mod_k<<<TOT_ROWS, 256>>>(x, n1w, moda, xn);

    // 3) QKV projections
    sgemm_k<0><<<dim3(8, 32), 256>>>(xn, wq, q, TOT_ROWS, DIMC, DIMC, nullptr, nullptr);
    sgemm_k<0><<<dim3(2, 32), 256>>>(xn, wk, k, TOT_ROWS, KVDIM, DIMC, nullptr, nullptr);
    sgemm_k<0><<<dim3(2, 32), 256>>>(xn, wv, v, TOT_ROWS, KVDIM, DIMC, nullptr, nullptr);

    // 4) RoPE (q: 4096*512 pairs, k: 4096*128 pairs)
    rope_k<<<(TOT_ROWS * 512 + TOT_ROWS * 128) / 256, 256>>>(q, k, fc, fs);

    // 5) block-causal attention
    attn_k<<<dim3(8, 16, 4), 128>>>(q, k, v, att);

    // 6) h = x + gate_a * (att @ wo^T)
    sgemm_k<2><<<dim3(8, 32), 256>>>(att, wo, h, TOT_ROWS, DIMC, DIMC, x, moda);

    // 7) hn = rmsnorm(h) * (1+scale_f) + shift_f
    rmsnorm_mod_k<<<TOT_ROWS, 256>>>(h, n2w, modf, hn);

    // 8) FFN: u = hn w1^T, g = hn w3^T, f = silu(u)*g
    sgemm_k<0><<<dim3(8, 32), 256>>>(hn, w1, u, TOT_ROWS, DIMC, DIMC, nullptr, nullptr);
    sgemm_k<0><<<dim3(8, 32), 256>>>(hn, w3, g, TOT_ROWS, DIMC, DIMC, nullptr, nullptr);
    silumul_k<<<(TOT_ROWS * DIMC) / 256, 256>>>(u, g, f, TOT_ROWS * DIMC);

    // 9) out = h + gate_f * (f @ w2^T)
    sgemm_k<2><<<dim3(8, 32), 256>>>(f, w2, out, TOT_ROWS, DIMC, DIMC, h, modf);
}

// round 12
// speedup vs baseline: 2.2388x; 2.2388x over previous
#include <cuda_runtime.h>
#include <cstdint>
#include <math.h>

// ---------------------------------------------------------------------------
// Problem constants
// ---------------------------------------------------------------------------
#define TOT_ROWS 4096           // B*S
#define DIMC     1024
#define KVDIM    256
#define MODM     512            // B*BLK_NUM
#define MODN     3072

// ---------------- scratch (device globals; no allocations) -----------------
__device__ float g_sv  [MODM * DIMC];
__device__ float g_moda[MODM * MODN];
__device__ float g_modf[MODM * MODN];
__device__ float g_xn  [TOT_ROWS * DIMC];
__device__ float g_q   [TOT_ROWS * DIMC];
__device__ float g_k   [TOT_ROWS * KVDIM];
__device__ float g_v   [TOT_ROWS * KVDIM];
__device__ float g_att [TOT_ROWS * DIMC];
__device__ float g_h   [TOT_ROWS * DIMC];
__device__ float g_hn  [TOT_ROWS * DIMC];
__device__ float g_u   [TOT_ROWS * DIMC];
__device__ float g_g   [TOT_ROWS * DIMC];
__device__ float g_f   [TOT_ROWS * DIMC];

// ---------------------------------------------------------------------------
// Helpers (all sm_80-baseline PTX: legal on the harness's sm_103 PTX target)
// ---------------------------------------------------------------------------
__device__ __forceinline__ uint32_t smem_u32(const void* p) {
    uint32_t a;
    asm("{ .reg .u64 t; cvta.to.shared.u64 t, %1; cvt.u32.u64 %0, t; }"
        : "=r"(a) : "l"(p));
    return a;
}

__device__ __forceinline__ void cp16(uint32_t dst, const void* src) {
    asm volatile("cp.async.cg.shared.global [%0], [%1], 16;"
                 :: "r"(dst), "l"(src) : "memory");
}
#define CP_COMMIT() asm volatile("cp.async.commit_group;" ::: "memory")
#define CP_WAIT0()  asm volatile("cp.async.wait_group 0;" ::: "memory")

__device__ __forceinline__ uint32_t f2tf32(float f) {
    uint32_t r;
    asm("cvt.rna.tf32.f32 %0, %1;" : "=r"(r) : "f"(f));
    return r;
}

__device__ __forceinline__ void mma_tf32(float* d, const uint32_t* a,
                                         uint32_t b0, uint32_t b1) {
    asm volatile(
        "mma.sync.aligned.m16n8k8.row.col.f32.tf32.tf32.f32 "
        "{%0,%1,%2,%3}, {%4,%5,%6,%7}, {%8,%9}, {%0,%1,%2,%3};"
        : "+f"(d[0]), "+f"(d[1]), "+f"(d[2]), "+f"(d[3])
        : "r"(a[0]), "r"(a[1]), "r"(a[2]), "r"(a[3]), "r"(b0), "r"(b1));
}

// ---------------------------------------------------------------------------
// Tensor-core tf32 GEMM: C[M,N] = A[M,K] * W[N,K]^T  (both row-major)
//   MODE 0: plain    MODE 1: + bias[n] (aux1)
//   MODE 2: C = aux1 + gate * acc, gate[n] = aux2[modrow*3072 + 2048 + n]
// CTA tile 128x128, BK=32, 8 warps (4 along M x 2 along N), warp tile 32x64.
// SMEM per stage: A 16KB + B 16KB; double buffered = 64KB dynamic.
// XOR swizzle: element (row,col) stored at col^((row&7)<<2)  (conflict-free
// for both float4 stores and the 8-row x 4-col fragment load pattern).
// Requires M%128==0, N%128==0, K%32==0.
// ---------------------------------------------------------------------------
#define TCG_SMEM (2 * 32768)

template <int MODE>
__global__ __launch_bounds__(256, 2)
void tc_gemm(const float* __restrict__ A, const float* __restrict__ B,
             float* __restrict__ C, int M, int N, int K,
             const float* __restrict__ aux1, const float* __restrict__ aux2)
{
    extern __shared__ char smem[];
    const uint32_t sbase = smem_u32(smem);

    const int tid  = threadIdx.x;
    const int wid  = tid >> 5;
    const int lane = tid & 31;
    const int g    = lane >> 2;        // 0..7
    const int t    = lane & 3;         // 0..3
    const int warpM = wid & 3;         // 0..3
    const int warpN = wid >> 2;        // 0..1
    const int bm = blockIdx.y * 128;
    const int bn = blockIdx.x * 128;

    // load task decomposition: 256 threads x 4 tasks = 128 rows x 8 float4
    const int lrow = tid >> 1;                       // base row stride trick unused; use task loop
    (void)lrow;

    float acc[2][8][4];
#pragma unroll
    for (int mi = 0; mi < 2; mi++)
#pragma unroll
        for (int ni = 0; ni < 8; ni++)
#pragma unroll
            for (int r = 0; r < 4; r++) acc[mi][ni][r] = 0.f;

    const int nch = K >> 5;

    // ---- async load of one 128x32 chunk pair into stage s ----
    auto load_chunk = [&](int ch, int s) {
        const int k0 = ch << 5;
        const uint32_t abase = sbase + s * 32768;
        const uint32_t bbase = abase + 16384;
#pragma unroll
        for (int u = 0; u < 4; u++) {
            const int task = tid + u * 256;          // 0..1023
            const int row  = task >> 3;              // 0..127
            const int q    = task & 7;               // 0..7
            const int qs   = q ^ (row & 7);          // float4-level swizzle
            const uint32_t off = (uint32_t)(row * 8 + qs) * 16;
            cp16(abase + off, A + (size_t)(bm + row) * K + k0 + q * 4);
            cp16(bbase + off, B + (size_t)(bn + row) * K + k0 + q * 4);
        }
        CP_COMMIT();
    };

    // prologue
    load_chunk(0, 0);
    CP_WAIT0();
    __syncthreads();

    const int sx = g << 2;             // per-lane swizzle XOR (row&7 == g for our rows)

    for (int ch = 0; ch < nch; ch++) {
        const int s = ch & 1;
        if (ch + 1 < nch) load_chunk(ch + 1, s ^ 1);

        const float* sA = (const float*)(smem + s * 32768);
        const float* sB = (const float*)(smem + s * 32768 + 16384);

#pragma unroll
        for (int ka = 0; ka < 4; ka++) {
            const int k0 = ka * 8;
            uint32_t a[2][4];
#pragma unroll
            for (int mi = 0; mi < 2; mi++) {
                const int r0 = warpM * 32 + mi * 16 + g;
                a[mi][0] = f2tf32(sA[r0 * 32       + ((k0 + t)     ^ sx)]);
                a[mi][1] = f2tf32(sA[(r0 + 8) * 32 + ((k0 + t)     ^ sx)]);
                a[mi][2] = f2tf32(sA[r0 * 32       + ((k0 + t + 4) ^ sx)]);
                a[mi][3] = f2tf32(sA[(r0 + 8) * 32 + ((k0 + t + 4) ^ sx)]);
            }
#pragma unroll
            for (int ni = 0; ni < 8; ni++) {
                const int c0 = warpN * 64 + ni * 8 + g;
                const uint32_t b0 = f2tf32(sB[c0 * 32 + ((k0 + t)     ^ sx)]);
                const uint32_t b1 = f2tf32(sB[c0 * 32 + ((k0 + t + 4) ^ sx)]);
                mma_tf32(acc[0][ni], a[0], b0, b1);
                mma_tf32(acc[1][ni], a[1], b0, b1);
            }
        }

        if (ch + 1 < nch) CP_WAIT0();
        __syncthreads();
    }

    // ---- epilogue: registers -> gmem (float2 per fragment half-row) ----
#pragma unroll
    for (int mi = 0; mi < 2; mi++) {
#pragma unroll
        for (int ni = 0; ni < 8; ni++) {
            const int row0 = bm + warpM * 32 + mi * 16 + g;
            const int row1 = row0 + 8;
            const int col  = bn + warpN * 64 + ni * 8 + t * 2;
            float2 v0 = make_float2(acc[mi][ni][0], acc[mi][ni][1]);
            float2 v1 = make_float2(acc[mi][ni][2], acc[mi][ni][3]);
            if (MODE == 0) {
                *(float2*)(C + (size_t)row0 * N + col) = v0;
                *(float2*)(C + (size_t)row1 * N + col) = v1;
            } else if (MODE == 1) {
                const float2 bi = *(const float2*)(aux1 + col);
                v0.x += bi.x; v0.y += bi.y;
                v1.x += bi.x; v1.y += bi.y;
                *(float2*)(C + (size_t)row0 * N + col) = v0;
                *(float2*)(C + (size_t)row1 * N + col) = v1;
            } else {
                const int mr0 = ((row0 >> 10) << 7) + ((row0 & 1023) >> 3);
                const int mr1 = ((row1 >> 10) << 7) + ((row1 & 1023) >> 3);
                const float2 gt0 = *(const float2*)(aux2 + (size_t)mr0 * MODN + 2048 + col);
                const float2 gt1 = *(const float2*)(aux2 + (size_t)mr1 * MODN + 2048 + col);
                const float2 rs0 = *(const float2*)(aux1 + (size_t)row0 * N + col);
                const float2 rs1 = *(const float2*)(aux1 + (size_t)row1 * N + col);
                v0.x = rs0.x + gt0.x * v0.x; v0.y = rs0.y + gt0.y * v0.y;
                v1.x = rs1.x + gt1.x * v1.x; v1.y = rs1.y + gt1.y * v1.y;
                *(float2*)(C + (size_t)row0 * N + col) = v0;
                *(float2*)(C + (size_t)row1 * N + col) = v1;
            }
        }
    }
}

// ---------------------------------------------------------------------------
// silu elementwise
// ---------------------------------------------------------------------------
__global__ void silu_k(const float* __restrict__ in, float* __restrict__ out, int n)
{
    int i = blockIdx.x * blockDim.x + threadIdx.x;
    if (i < n) {
        float v = in[i];
        out[i] = v / (1.f + __expf(-v));
    }
}

__global__ void silumul_k(const float* __restrict__ u, const float* __restrict__ g,
                          float* __restrict__ f, int n)
{
    int i = blockIdx.x * blockDim.x + threadIdx.x;
    if (i < n) {
        float v = u[i];
        f[i] = (v / (1.f + __expf(-v))) * g[i];
    }
}

// ---------------------------------------------------------------------------
// Fused rmsnorm + adaLN modulation
// ---------------------------------------------------------------------------
__global__ __launch_bounds__(256)
void rmsnorm_mod_k(const float* __restrict__ X, const float* __restrict__ w,
                   const float* __restrict__ mod, float* __restrict__ Y)
{
    const int row = blockIdx.x;
    const int modrow = ((row >> 10) << 7) + ((row & 1023) >> 3);
    const float* x  = X + (size_t)row * DIMC;
    const float* sh = mod + (size_t)modrow * MODN;
    const float* sc = sh + 1024;
    const int t = threadIdx.x;

    float4 xv = *(const float4*)(x + t * 4);
    float ss = xv.x * xv.x + xv.y * xv.y + xv.z * xv.z + xv.w * xv.w;
#pragma unroll
    for (int o = 16; o > 0; o >>= 1) ss += __shfl_xor_sync(0xffffffffu, ss, o);

    __shared__ float red[8];
    if ((t & 31) == 0) red[t >> 5] = ss;
    __syncthreads();
    float tot = 0.f;
#pragma unroll
    for (int i = 0; i < 8; i++) tot += red[i];

    float rinv = rsqrtf(tot * (1.f / 1024.f) + 1e-6f);
    float4 wv = *(const float4*)(w + t * 4);
    float4 scv = *(const float4*)(sc + t * 4);
    float4 shv = *(const float4*)(sh + t * 4);
    float4 yv;
    yv.x = xv.x * rinv * wv.x * (1.f + scv.x) + shv.x;
    yv.y = xv.y * rinv * wv.y * (1.f + scv.y) + shv.y;
    yv.z = xv.z * rinv * wv.z * (1.f + scv.z) + shv.z;
    yv.w = xv.w * rinv * wv.w * (1.f + scv.w) + shv.w;
    *(float4*)(Y + (size_t)row * DIMC + t * 4) = yv;
}

// ---------------------------------------------------------------------------
// RoPE in-place
// ---------------------------------------------------------------------------
__global__ void rope_k(float* __restrict__ q, float* __restrict__ k,
                       const float* __restrict__ fc, const float* __restrict__ fs)
{
    const int nq = TOT_ROWS * 512;
    int idx = blockIdx.x * blockDim.x + threadIdx.x;
    if (idx < nq) {
        int row = idx >> 9;
        int p = idx & 511;
        int head = p >> 5, i = p & 31;
        int s = row & 1023;
        float c = fc[s * 32 + i], sn = fs[s * 32 + i];
        float* base = q + (size_t)row * DIMC + head * 64 + i * 2;
        float x1 = base[0], x2 = base[1];
        base[0] = x1 * c - x2 * sn;
        base[1] = x1 * sn + x2 * c;
    } else {
        int j = idx - nq;
        int row = j >> 7;
        int p = j & 127;
        int head = p >> 5, i = p & 31;
        int s = row & 1023;
        float c = fc[s * 32 + i], sn = fs[s * 32 + i];
        float* base = k + (size_t)row * KVDIM + head * 64 + i * 2;
        float x1 = base[0], x2 = base[1];
        base[0] = x1 * c - x2 * sn;
        base[1] = x1 * sn + x2 * c;
    }
}

// ---------------------------------------------------------------------------
// Block-causal flash attention (unchanged this round)
// ---------------------------------------------------------------------------
__global__ __launch_bounds__(128, 2)
void attn_k(const float* __restrict__ Q, const float* __restrict__ K,
            const float* __restrict__ V, float* __restrict__ O)
{
    const int qt = blockIdx.x, h = blockIdx.y, b = blockIdx.z;
    const int kvh = h >> 2;
    const int q0 = qt * 128;
    const int r = q0 + threadIdx.x;
    const int grow = b * 1024 + r;

    __shared__ float ks[32][64];
    __shared__ float vs[32][64];

    float4 qf[16], of[16];
    const float4* qp = (const float4*)(Q + (size_t)grow * DIMC + h * 64);
#pragma unroll
    for (int i = 0; i < 16; i++) { qf[i] = qp[i]; of[i] = make_float4(0.f, 0.f, 0.f, 0.f); }

    float m = -1e30f, l = 0.f;
    const int lim = r - (r & 7) + 8;
    const int kend = q0 + 128;
    const float scale = 0.125f;

    const int jr = threadIdx.x >> 2;
    const int jc = (threadIdx.x & 3) * 16;

    for (int kc = 0; kc < kend; kc += 32) {
        const float4* kp = (const float4*)(K + (size_t)(b * 1024 + kc + jr) * KVDIM + kvh * 64 + jc);
        const float4* vp = (const float4*)(V + (size_t)(b * 1024 + kc + jr) * KVDIM + kvh * 64 + jc);
        float4* ksd = (float4*)&ks[jr][jc];
        float4* vsd = (float4*)&vs[jr][jc];
#pragma unroll
        for (int uu = 0; uu < 4; uu++) { ksd[uu] = kp[uu]; vsd[uu] = vp[uu]; }
        __syncthreads();

        float sc[32];
#pragma unroll
        for (int j = 0; j < 32; j++) {
            const float4* kr = (const float4*)ks[j];
            float s = 0.f;
#pragma unroll
            for (int d = 0; d < 16; d++) {
                float4 kv4 = kr[d];
                s += qf[d].x * kv4.x + qf[d].y * kv4.y + qf[d].z * kv4.z + qf[d].w * kv4.w;
            }
            int kg = kc + j;
            sc[j] = (kg < lim) ? s * scale : -1e30f;
        }

        float mnew = m;
#pragma unroll
        for (int j = 0; j < 32; j++) mnew = fmaxf(mnew, sc[j]);
        float corr = __expf(m - mnew);
        l *= corr;
#pragma unroll
        for (int i = 0; i < 16; i++) {
            of[i].x *= corr; of[i].y *= corr; of[i].z *= corr; of[i].w *= corr;
        }
#pragma unroll
        for (int j = 0; j < 32; j++) {
            float p = __expf(sc[j] - mnew);
            l += p;
            const float4* vr = (const float4*)vs[j];
#pragma unroll
            for (int d = 0; d < 16; d++) {
                float4 vv = vr[d];
                of[d].x += p * vv.x; of[d].y += p * vv.y;
                of[d].z += p * vv.z; of[d].w += p * vv.w;
            }
        }
        m = mnew;
        __syncthreads();
    }

    float inv = 1.f / l;
    float4* op = (float4*)(O + (size_t)grow * DIMC + h * 64);
#pragma unroll
    for (int i = 0; i < 16; i++) {
        float4 o4;
        o4.x = of[i].x * inv; o4.y = of[i].y * inv;
        o4.z = of[i].z * inv; o4.w = of[i].w * inv;
        op[i] = o4;
    }
}

// ---------------------------------------------------------------------------
// Launcher
// ---------------------------------------------------------------------------
extern "C" void kernel_launch(void* const* d_in, const int* in_sizes, int n_in,
                              void* d_out, int out_size)
{
    (void)in_sizes; (void)n_in; (void)out_size;
    const float* x   = (const float*)d_in[0];
    const float* vec = (const float*)d_in[1];
    const float* wq  = (const float*)d_in[2];
    const float* wk  = (const float*)d_in[3];
    const float* wv  = (const float*)d_in[4];
    const float* wv_ = wv;
    const float* wo  = (const float*)d_in[5];
    const float* w1  = (const float*)d_in[6];
    const float* w2  = (const float*)d_in[7];
    const float* w3  = (const float*)d_in[8];
    const float* maw = (const float*)d_in[9];
    const float* mab = (const float*)d_in[10];
    const float* mfw = (const float*)d_in[11];
    const float* mfb = (const float*)d_in[12];
    const float* n1w = (const float*)d_in[13];
    const float* n2w = (const float*)d_in[14];
    const float* fc  = (const float*)d_in[15];
    const float* fs  = (const float*)d_in[16];
    (void)wv_;
    float* out = (float*)d_out;

    float *sv, *moda, *modf, *xn, *q, *k, *v, *att, *h, *hn, *u, *g, *f;
    cudaGetSymbolAddress((void**)&sv,   g_sv);
    cudaGetSymbolAddress((void**)&moda, g_moda);
    cudaGetSymbolAddress((void**)&modf, g_modf);
    cudaGetSymbolAddress((void**)&xn,   g_xn);
    cudaGetSymbolAddress((void**)&q,    g_q);
    cudaGetSymbolAddress((void**)&k,    g_k);
    cudaGetSymbolAddress((void**)&v,    g_v);
    cudaGetSymbolAddress((void**)&att,  g_att);
    cudaGetSymbolAddress((void**)&h,    g_h);
    cudaGetSymbolAddress((void**)&hn,   g_hn);
    cudaGetSymbolAddress((void**)&u,    g_u);
    cudaGetSymbolAddress((void**)&g,    g_g);
    cudaGetSymbolAddress((void**)&f,    g_f);

    cudaFuncSetAttribute(tc_gemm<0>, cudaFuncAttributeMaxDynamicSharedMemorySize, TCG_SMEM);
    cudaFuncSetAttribute(tc_gemm<1>, cudaFuncAttributeMaxDynamicSharedMemorySize, TCG_SMEM);
    cudaFuncSetAttribute(tc_gemm<2>, cudaFuncAttributeMaxDynamicSharedMemorySize, TCG_SMEM);

    // 1) modulation: silu(vec) then two (512,3072,1024) GEMMs with bias
    silu_k<<<(MODM * DIMC) / 256, 256>>>(vec, sv, MODM * DIMC);
    tc_gemm<1><<<dim3(MODN / 128, MODM / 128), 256, TCG_SMEM>>>(sv, maw, moda, MODM, MODN, DIMC, mab, nullptr);
    tc_gemm<1><<<dim3(MODN / 128, MODM / 128), 256, TCG_SMEM>>>(sv, mfw, modf, MODM, MODN, DIMC, mfb, nullptr);

    // 2) xn = rmsnorm(x) * (1+scale_a) + shift_a
    rmsnorm_mod_k<<<TOT_ROWS, 256>>>(x, n1w, moda, xn);

    // 3) QKV projections
    tc_gemm<0><<<dim3(8, 32), 256, TCG_SMEM>>>(xn, wq, q, TOT_ROWS, DIMC, DIMC, nullptr, nullptr);
    tc_gemm<0><<<dim3(2, 32), 256, TCG_SMEM>>>(xn, wk, k, TOT_ROWS, KVDIM, DIMC, nullptr, nullptr);
    tc_gemm<0><<<dim3(2, 32), 256, TCG_SMEM>>>(xn, wv, v, TOT_ROWS, KVDIM, DIMC, nullptr, nullptr);

    // 4) RoPE
    rope_k<<<(TOT_ROWS * 512 + TOT_ROWS * 128) / 256, 256>>>(q, k, fc, fs);

    // 5) block-causal attention
    attn_k<<<dim3(8, 16, 4), 128>>>(q, k, v, att);

    // 6) h = x + gate_a * (att @ wo^T)
    tc_gemm<2><<<dim3(8, 32), 256, TCG_SMEM>>>(att, wo, h, TOT_ROWS, DIMC, DIMC, x, moda);

    // 7) hn = rmsnorm(h) * (1+scale_f) + shift_f
    rmsnorm_mod_k<<<TOT_ROWS, 256>>>(h, n2w, modf, hn);

    // 8) FFN
    tc_gemm<0><<<dim3(8, 32), 256, TCG_SMEM>>>(hn, w1, u, TOT_ROWS, DIMC, DIMC, nullptr, nullptr);
    tc_gemm<0><<<dim3(8, 32), 256, TCG_SMEM>>>(hn, w3, g, TOT_ROWS, DIMC, DIMC, nullptr, nullptr);
    silumul_k<<<(TOT_ROWS * DIMC) / 256, 256>>>(u, g, f, TOT_ROWS * DIMC);

    // 9) out = h + gate_f * (f @ w2^T)
    tc_gemm<2><<<dim3(8, 32), 256, TCG_SMEM>>>(f, w2, out, TOT_ROWS, DIMC, DIMC, h, modf);
}

// round 15
// speedup vs baseline: 4.0438x; 1.8062x over previous
#include <cuda_runtime.h>
#include <cstdint>
#include <math.h>

// ---------------------------------------------------------------------------
// Problem constants
// ---------------------------------------------------------------------------
#define TOT_ROWS 4096           // B*S
#define DIMC     1024
#define KVDIM    256
#define MODM     512            // B*BLK_NUM
#define MODN     3072

// ---------------- scratch (device globals; no allocations) -----------------
__device__ float g_sv  [MODM * DIMC];
__device__ float g_moda[MODM * MODN];
__device__ float g_modf[MODM * MODN];
__device__ float g_xn  [TOT_ROWS * DIMC];
__device__ float g_q   [TOT_ROWS * DIMC];
__device__ float g_k   [TOT_ROWS * KVDIM];
__device__ float g_v   [TOT_ROWS * KVDIM];
__device__ float g_att [TOT_ROWS * DIMC];
__device__ float g_h   [TOT_ROWS * DIMC];
__device__ float g_hn  [TOT_ROWS * DIMC];
__device__ float g_u   [TOT_ROWS * DIMC];
__device__ float g_g   [TOT_ROWS * DIMC];
__device__ float g_f   [TOT_ROWS * DIMC];

// ---------------------------------------------------------------------------
// Helpers (sm_80-baseline PTX: legal on the harness's sm_103 PTX target)
// ---------------------------------------------------------------------------
__device__ __forceinline__ uint32_t smem_u32(const void* p) {
    uint32_t a;
    asm("{ .reg .u64 t; cvta.to.shared.u64 t, %1; cvt.u32.u64 %0, t; }"
        : "=r"(a) : "l"(p));
    return a;
}

__device__ __forceinline__ void cp16(uint32_t dst, const void* src) {
    asm volatile("cp.async.cg.shared.global [%0], [%1], 16;"
                 :: "r"(dst), "l"(src) : "memory");
}
#define CP_COMMIT() asm volatile("cp.async.commit_group;" ::: "memory")
#define CP_WAIT0()  asm volatile("cp.async.wait_group 0;" ::: "memory")

__device__ __forceinline__ uint32_t f2tf32(float f) {
    uint32_t r;
    asm("cvt.rna.tf32.f32 %0, %1;" : "=r"(r) : "f"(f));
    return r;
}

__device__ __forceinline__ void mma_tf32(float* d, const uint32_t* a,
                                         uint32_t b0, uint32_t b1) {
    asm volatile(
        "mma.sync.aligned.m16n8k8.row.col.f32.tf32.tf32.f32 "
        "{%0,%1,%2,%3}, {%4,%5,%6,%7}, {%8,%9}, {%0,%1,%2,%3};"
        : "+f"(d[0]), "+f"(d[1]), "+f"(d[2]), "+f"(d[3])
        : "r"(a[0]), "r"(a[1]), "r"(a[2]), "r"(a[3]), "r"(b0), "r"(b1));
}

// ---------------------------------------------------------------------------
// Tensor-core tf32 GEMM: C[M,N] = A[M,K] * W[N,K]^T  (both row-major)
//   MODE 0: plain    MODE 1: + bias[n] (aux1)
//   MODE 2: C = aux1 + gate * acc, gate[n] = aux2[modrow*3072 + 2048 + n]
// ---------------------------------------------------------------------------
#define TCG_SMEM (2 * 32768)

template <int MODE>
__global__ __launch_bounds__(256, 2)
void tc_gemm(const float* __restrict__ A, const float* __restrict__ B,
             float* __restrict__ C, int M, int N, int K,
             const float* __restrict__ aux1, const float* __restrict__ aux2)
{
    extern __shared__ char smem[];
    const uint32_t sbase = smem_u32(smem);

    const int tid  = threadIdx.x;
    const int wid  = tid >> 5;
    const int lane = tid & 31;
    const int g    = lane >> 2;
    const int t    = lane & 3;
    const int warpM = wid & 3;
    const int warpN = wid >> 2;
    const int bm = blockIdx.y * 128;
    const int bn = blockIdx.x * 128;

    float acc[2][8][4];
#pragma unroll
    for (int mi = 0; mi < 2; mi++)
#pragma unroll
        for (int ni = 0; ni < 8; ni++)
#pragma unroll
            for (int r = 0; r < 4; r++) acc[mi][ni][r] = 0.f;

    const int nch = K >> 5;

    auto load_chunk = [&](int ch, int s) {
        const int k0 = ch << 5;
        const uint32_t abase = sbase + s * 32768;
        const uint32_t bbase = abase + 16384;
#pragma unroll
        for (int u = 0; u < 4; u++) {
            const int task = tid + u * 256;
            const int row  = task >> 3;
            const int q    = task & 7;
            const int qs   = q ^ (row & 7);
            const uint32_t off = (uint32_t)(row * 8 + qs) * 16;
            cp16(abase + off, A + (size_t)(bm + row) * K + k0 + q * 4);
            cp16(bbase + off, B + (size_t)(bn + row) * K + k0 + q * 4);
        }
        CP_COMMIT();
    };

    load_chunk(0, 0);
    CP_WAIT0();
    __syncthreads();

    const int sx = g << 2;

    for (int ch = 0; ch < nch; ch++) {
        const int s = ch & 1;
        if (ch + 1 < nch) load_chunk(ch + 1, s ^ 1);

        const float* sA = (const float*)(smem + s * 32768);
        const float* sB = (const float*)(smem + s * 32768 + 16384);

#pragma unroll
        for (int ka = 0; ka < 4; ka++) {
            const int k0 = ka * 8;
            uint32_t a[2][4];
#pragma unroll
            for (int mi = 0; mi < 2; mi++) {
                const int r0 = warpM * 32 + mi * 16 + g;
                a[mi][0] = f2tf32(sA[r0 * 32       + ((k0 + t)     ^ sx)]);
                a[mi][1] = f2tf32(sA[(r0 + 8) * 32 + ((k0 + t)     ^ sx)]);
                a[mi][2] = f2tf32(sA[r0 * 32       + ((k0 + t + 4) ^ sx)]);
                a[mi][3] = f2tf32(sA[(r0 + 8) * 32 + ((k0 + t + 4) ^ sx)]);
            }
#pragma unroll
            for (int ni = 0; ni < 8; ni++) {
                const int c0 = warpN * 64 + ni * 8 + g;
                const uint32_t b0 = f2tf32(sB[c0 * 32 + ((k0 + t)     ^ sx)]);
                const uint32_t b1 = f2tf32(sB[c0 * 32 + ((k0 + t + 4) ^ sx)]);
                mma_tf32(acc[0][ni], a[0], b0, b1);
                mma_tf32(acc[1][ni], a[1], b0, b1);
            }
        }

        if (ch + 1 < nch) CP_WAIT0();
        __syncthreads();
    }

#pragma unroll
    for (int mi = 0; mi < 2; mi++) {
#pragma unroll
        for (int ni = 0; ni < 8; ni++) {
            const int row0 = bm + warpM * 32 + mi * 16 + g;
            const int row1 = row0 + 8;
            const int col  = bn + warpN * 64 + ni * 8 + t * 2;
            float2 v0 = make_float2(acc[mi][ni][0], acc[mi][ni][1]);
            float2 v1 = make_float2(acc[mi][ni][2], acc[mi][ni][3]);
            if (MODE == 0) {
                *(float2*)(C + (size_t)row0 * N + col) = v0;
                *(float2*)(C + (size_t)row1 * N + col) = v1;
            } else if (MODE == 1) {
                const float2 bi = *(const float2*)(aux1 + col);
                v0.x += bi.x; v0.y += bi.y;
                v1.x += bi.x; v1.y += bi.y;
                *(float2*)(C + (size_t)row0 * N + col) = v0;
                *(float2*)(C + (size_t)row1 * N + col) = v1;
            } else {
                const int mr0 = ((row0 >> 10) << 7) + ((row0 & 1023) >> 3);
                const int mr1 = ((row1 >> 10) << 7) + ((row1 & 1023) >> 3);
                const float2 gt0 = *(const float2*)(aux2 + (size_t)mr0 * MODN + 2048 + col);
                const float2 gt1 = *(const float2*)(aux2 + (size_t)mr1 * MODN + 2048 + col);
                const float2 rs0 = *(const float2*)(aux1 + (size_t)row0 * N + col);
                const float2 rs1 = *(const float2*)(aux1 + (size_t)row1 * N + col);
                v0.x = rs0.x + gt0.x * v0.x; v0.y = rs0.y + gt0.y * v0.y;
                v1.x = rs1.x + gt1.x * v1.x; v1.y = rs1.y + gt1.y * v1.y;
                *(float2*)(C + (size_t)row0 * N + col) = v0;
                *(float2*)(C + (size_t)row1 * N + col) = v1;
            }
        }
    }
}

// ---------------------------------------------------------------------------
// Tensor-core block-causal flash attention.
// CTA = (qtile of 64 rows, head, batch); 128 threads = 4 warps.
// Warp w owns query rows [qt*64 + w*16, +16) for BOTH GEMMs, so the softmaxed
// P tile is warp-private (bounced via per-warp SMEM, __syncwarp only).
// K chunk staged [key][dim] stride 68 (bank-free B-frag loads);
// V chunk staged [kv][dim]  stride 72 (bank-free B-frag loads);
// double-buffered cp.async.  Chunks kc = 0..qt; only kc==qt needs masking,
// and the 8-granularity mask reduces to: allow n-atom na <= wid*2 (+1).
// ---------------------------------------------------------------------------
#define KST 68
#define VST 72
#define ATT_SMEM ((2 * 64 * KST + 2 * 64 * VST + 4 * 16 * KST) * 4)

__global__ __launch_bounds__(128, 2)
void attn_tc(const float* __restrict__ Q, const float* __restrict__ K,
             const float* __restrict__ V, float* __restrict__ O)
{
    extern __shared__ float sm[];
    const uint32_t sbase = smem_u32(sm);

    const int qt = blockIdx.x, h = blockIdx.y, b = blockIdx.z;
    const int kvh = h >> 2;
    const int tid = threadIdx.x;
    const int wid = tid >> 5;
    const int lane = tid & 31;
    const int g = lane >> 2;
    const int t = lane & 3;

    // SMEM offsets (floats)
    const int K0 = 0, K1 = 64 * KST;
    const int V0 = 2 * 64 * KST, V1 = V0 + 64 * VST;
    float* sP = sm + 2 * 64 * KST + 2 * 64 * VST + wid * (16 * KST);

    // ---- Q fragments (pre-scaled by 1/sqrt(64)), loaded once ----
    const float* qb = Q + (size_t)(b * 1024 + qt * 64 + wid * 16) * DIMC + h * 64;
    uint32_t qa[8][4];
#pragma unroll
    for (int ka = 0; ka < 8; ka++) {
        const int c = ka * 8;
        qa[ka][0] = f2tf32(0.125f * qb[(size_t)g * DIMC + c + t]);
        qa[ka][1] = f2tf32(0.125f * qb[(size_t)(g + 8) * DIMC + c + t]);
        qa[ka][2] = f2tf32(0.125f * qb[(size_t)g * DIMC + c + t + 4]);
        qa[ka][3] = f2tf32(0.125f * qb[(size_t)(g + 8) * DIMC + c + t + 4]);
    }

    float oacc[8][4];
#pragma unroll
    for (int na = 0; na < 8; na++)
#pragma unroll
        for (int r = 0; r < 4; r++) oacc[na][r] = 0.f;
    float m0 = -1e30f, m1 = -1e30f, l0 = 0.f, l1 = 0.f;

    auto load_kv = [&](int kc, int s) {
        const float* kb = K + (size_t)(b * 1024 + kc * 64) * KVDIM + kvh * 64;
        const float* vb = V + (size_t)(b * 1024 + kc * 64) * KVDIM + kvh * 64;
        const uint32_t kst = sbase + (s ? K1 : K0) * 4;
        const uint32_t vst = sbase + (s ? V1 : V0) * 4;
#pragma unroll
        for (int u = 0; u < 8; u++) {
            const int task = tid + u * 128;       // 0..1023
            const int row  = task >> 4;           // 0..63
            const int q4   = task & 15;           // 0..15
            cp16(kst + (uint32_t)(row * KST + q4 * 4) * 4, kb + (size_t)row * KVDIM + q4 * 4);
            cp16(vst + (uint32_t)(row * VST + q4 * 4) * 4, vb + (size_t)row * KVDIM + q4 * 4);
        }
        CP_COMMIT();
    };

    load_kv(0, 0);
    CP_WAIT0();
    __syncthreads();

    for (int kc = 0; kc <= qt; kc++) {
        const int s = kc & 1;
        if (kc < qt) load_kv(kc + 1, s ^ 1);

        const float* sK = sm + (s ? K1 : K0);
        const float* sV = sm + (s ? V1 : V0);

        // ---- S = Q * K^T ----
        float sacc[8][4];
#pragma unroll
        for (int na = 0; na < 8; na++)
#pragma unroll
            for (int r = 0; r < 4; r++) sacc[na][r] = 0.f;

#pragma unroll
        for (int ka = 0; ka < 8; ka++) {
            const int k0 = ka * 8;
#pragma unroll
            for (int na = 0; na < 8; na++) {
                const int n0 = na * 8 + g;
                const uint32_t b0 = f2tf32(sK[n0 * KST + k0 + t]);
                const uint32_t b1 = f2tf32(sK[n0 * KST + k0 + t + 4]);
                mma_tf32(sacc[na], qa[ka], b0, b1);
            }
        }

        // ---- diagonal-chunk mask (8-granularity block causal) ----
        if (kc == qt) {
            const int rb0 = wid * 2;       // row-block of rows g   (local)
            const int rb1 = rb0 + 1;       // row-block of rows g+8
#pragma unroll
            for (int na = 0; na < 8; na++) {
                if (na > rb0) { sacc[na][0] = -1e30f; sacc[na][1] = -1e30f; }
                if (na > rb1) { sacc[na][2] = -1e30f; sacc[na][3] = -1e30f; }
            }
        }

        // ---- online softmax ----
        float mx0 = -1e30f, mx1 = -1e30f;
#pragma unroll
        for (int na = 0; na < 8; na++) {
            mx0 = fmaxf(mx0, fmaxf(sacc[na][0], sacc[na][1]));
            mx1 = fmaxf(mx1, fmaxf(sacc[na][2], sacc[na][3]));
        }
        mx0 = fmaxf(mx0, __shfl_xor_sync(0xffffffffu, mx0, 1));
        mx0 = fmaxf(mx0, __shfl_xor_sync(0xffffffffu, mx0, 2));
        mx1 = fmaxf(mx1, __shfl_xor_sync(0xffffffffu, mx1, 1));
        mx1 = fmaxf(mx1, __shfl_xor_sync(0xffffffffu, mx1, 2));

        const float mn0 = fmaxf(m0, mx0);
        const float mn1 = fmaxf(m1, mx1);
        const float c0 = __expf(m0 - mn0);
        const float c1 = __expf(m1 - mn1);
        l0 *= c0; l1 *= c1;
#pragma unroll
        for (int na = 0; na < 8; na++) {
            oacc[na][0] *= c0; oacc[na][1] *= c0;
            oacc[na][2] *= c1; oacc[na][3] *= c1;
        }
#pragma unroll
        for (int na = 0; na < 8; na++) {
            const float p0 = __expf(sacc[na][0] - mn0);
            const float p1 = __expf(sacc[na][1] - mn0);
            const float p2 = __expf(sacc[na][2] - mn1);
            const float p3 = __expf(sacc[na][3] - mn1);
            l0 += p0 + p1;
            l1 += p2 + p3;
            sP[g * KST + na * 8 + 2 * t]           = p0;
            sP[g * KST + na * 8 + 2 * t + 1]       = p1;
            sP[(g + 8) * KST + na * 8 + 2 * t]     = p2;
            sP[(g + 8) * KST + na * 8 + 2 * t + 1] = p3;
        }
        m0 = mn0; m1 = mn1;
        __syncwarp();

        // ---- O += P * V ----
#pragma unroll
        for (int ka = 0; ka < 8; ka++) {
            uint32_t pa[4];
            pa[0] = f2tf32(sP[g * KST + ka * 8 + t]);
            pa[1] = f2tf32(sP[(g + 8) * KST + ka * 8 + t]);
            pa[2] = f2tf32(sP[g * KST + ka * 8 + t + 4]);
            pa[3] = f2tf32(sP[(g + 8) * KST + ka * 8 + t + 4]);
#pragma unroll
            for (int na = 0; na < 8; na++) {
                const uint32_t b0 = f2tf32(sV[(ka * 8 + t) * VST + na * 8 + g]);
                const uint32_t b1 = f2tf32(sV[(ka * 8 + t + 4) * VST + na * 8 + g]);
                mma_tf32(oacc[na], pa, b0, b1);
            }
        }
        __syncwarp();

        if (kc < qt) CP_WAIT0();
        __syncthreads();
    }

    // ---- finalize ----
    l0 += __shfl_xor_sync(0xffffffffu, l0, 1);
    l0 += __shfl_xor_sync(0xffffffffu, l0, 2);
    l1 += __shfl_xor_sync(0xffffffffu, l1, 1);
    l1 += __shfl_xor_sync(0xffffffffu, l1, 2);
    const float i0 = 1.f / l0;
    const float i1 = 1.f / l1;

    const size_t r0 = (size_t)(b * 1024 + qt * 64 + wid * 16 + g);
    const size_t r1 = r0 + 8;
#pragma unroll
    for (int na = 0; na < 8; na++) {
        const int col = h * 64 + na * 8 + 2 * t;
        *(float2*)(O + r0 * DIMC + col) = make_float2(oacc[na][0] * i0, oacc[na][1] * i0);
        *(float2*)(O + r1 * DIMC + col) = make_float2(oacc[na][2] * i1, oacc[na][3] * i1);
    }
}

// ---------------------------------------------------------------------------
// silu elementwise
// ---------------------------------------------------------------------------
__global__ void silu_k(const float* __restrict__ in, float* __restrict__ out, int n)
{
    int i = blockIdx.x * blockDim.x + threadIdx.x;
    if (i < n) {
        float v = in[i];
        out[i] = v / (1.f + __expf(-v));
    }
}

__global__ void silumul_k(const float* __restrict__ u, const float* __restrict__ g,
                          float* __restrict__ f, int n)
{
    int i = blockIdx.x * blockDim.x + threadIdx.x;
    if (i < n) {
        float v = u[i];
        f[i] = (v / (1.f + __expf(-v))) * g[i];
    }
}

// ---------------------------------------------------------------------------
// Fused rmsnorm + adaLN modulation
// ---------------------------------------------------------------------------
__global__ __launch_bounds__(256)
void rmsnorm_mod_k(const float* __restrict__ X, const float* __restrict__ w,
                   const float* __restrict__ mod, float* __restrict__ Y)
{
    const int row = blockIdx.x;
    const int modrow = ((row >> 10) << 7) + ((row & 1023) >> 3);
    const float* x  = X + (size_t)row * DIMC;
    const float* sh = mod + (size_t)modrow * MODN;
    const float* sc = sh + 1024;
    const int t = threadIdx.x;

    float4 xv = *(const float4*)(x + t * 4);
    float ss = xv.x * xv.x + xv.y * xv.y + xv.z * xv.z + xv.w * xv.w;
#pragma unroll
    for (int o = 16; o > 0; o >>= 1) ss += __shfl_xor_sync(0xffffffffu, ss, o);

    __shared__ float red[8];
    if ((t & 31) == 0) red[t >> 5] = ss;
    __syncthreads();
    float tot = 0.f;
#pragma unroll
    for (int i = 0; i < 8; i++) tot += red[i];

    float rinv = rsqrtf(tot * (1.f / 1024.f) + 1e-6f);
    float4 wv = *(const float4*)(w + t * 4);
    float4 scv = *(const float4*)(sc + t * 4);
    float4 shv = *(const float4*)(sh + t * 4);
    float4 yv;
    yv.x = xv.x * rinv * wv.x * (1.f + scv.x) + shv.x;
    yv.y = xv.y * rinv * wv.y * (1.f + scv.y) + shv.y;
    yv.z = xv.z * rinv * wv.z * (1.f + scv.z) + shv.z;
    yv.w = xv.w * rinv * wv.w * (1.f + scv.w) + shv.w;
    *(float4*)(Y + (size_t)row * DIMC + t * 4) = yv;
}

// ---------------------------------------------------------------------------
// RoPE in-place
// ---------------------------------------------------------------------------
__global__ void rope_k(float* __restrict__ q, float* __restrict__ k,
                       const float* __restrict__ fc, const float* __restrict__ fs)
{
    const int nq = TOT_ROWS * 512;
    int idx = blockIdx.x * blockDim.x + threadIdx.x;
    if (idx < nq) {
        int row = idx >> 9;
        int p = idx & 511;
        int head = p >> 5, i = p & 31;
        int s = row & 1023;
        float c = fc[s * 32 + i], sn = fs[s * 32 + i];
        float* base = q + (size_t)row * DIMC + head * 64 + i * 2;
        float x1 = base[0], x2 = base[1];
        base[0] = x1 * c - x2 * sn;
        base[1] = x1 * sn + x2 * c;
    } else {
        int j = idx - nq;
        int row = j >> 7;
        int p = j & 127;
        int head = p >> 5, i = p & 31;
        int s = row & 1023;
        float c = fc[s * 32 + i], sn = fs[s * 32 + i];
        float* base = k + (size_t)row * KVDIM + head * 64 + i * 2;
        float x1 = base[0], x2 = base[1];
        base[0] = x1 * c - x2 * sn;
        base[1] = x1 * sn + x2 * c;
    }
}

// ---------------------------------------------------------------------------
// Launcher
// ---------------------------------------------------------------------------
extern "C" void kernel_launch(void* const* d_in, const int* in_sizes, int n_in,
                              void* d_out, int out_size)
{
    (void)in_sizes; (void)n_in; (void)out_size;
    const float* x   = (const float*)d_in[0];
    const float* vec = (const float*)d_in[1];
    const float* wq  = (const float*)d_in[2];
    const float* wk  = (const float*)d_in[3];
    const float* wv  = (const float*)d_in[4];
    const float* wo  = (const float*)d_in[5];
    const float* w1  = (const float*)d_in[6];
    const float* w2  = (const float*)d_in[7];
    const float* w3  = (const float*)d_in[8];
    const float* maw = (const float*)d_in[9];
    const float* mab = (const float*)d_in[10];
    const float* mfw = (const float*)d_in[11];
    const float* mfb = (const float*)d_in[12];
    const float* n1w = (const float*)d_in[13];
    const float* n2w = (const float*)d_in[14];
    const float* fc  = (const float*)d_in[15];
    const float* fs  = (const float*)d_in[16];
    float* out = (float*)d_out;

    float *sv, *moda, *modf, *xn, *q, *k, *v, *att, *h, *hn, *u, *g, *f;
    cudaGetSymbolAddress((void**)&sv,   g_sv);
    cudaGetSymbolAddress((void**)&moda, g_moda);
    cudaGetSymbolAddress((void**)&modf, g_modf);
    cudaGetSymbolAddress((void**)&xn,   g_xn);
    cudaGetSymbolAddress((void**)&q,    g_q);
    cudaGetSymbolAddress((void**)&k,    g_k);
    cudaGetSymbolAddress((void**)&v,    g_v);
    cudaGetSymbolAddress((void**)&att,  g_att);
    cudaGetSymbolAddress((void**)&h,    g_h);
    cudaGetSymbolAddress((void**)&hn,   g_hn);
    cudaGetSymbolAddress((void**)&u,    g_u);
    cudaGetSymbolAddress((void**)&g,    g_g);
    cudaGetSymbolAddress((void**)&f,    g_f);

    cudaFuncSetAttribute(tc_gemm<0>, cudaFuncAttributeMaxDynamicSharedMemorySize, TCG_SMEM);
    cudaFuncSetAttribute(tc_gemm<1>, cudaFuncAttributeMaxDynamicSharedMemorySize, TCG_SMEM);
    cudaFuncSetAttribute(tc_gemm<2>, cudaFuncAttributeMaxDynamicSharedMemorySize, TCG_SMEM);
    cudaFuncSetAttribute(attn_tc,    cudaFuncAttributeMaxDynamicSharedMemorySize, ATT_SMEM);

    // 1) modulation: silu(vec) then two (512,3072,1024) GEMMs with bias
    silu_k<<<(MODM * DIMC) / 256, 256>>>(vec, sv, MODM * DIMC);
    tc_gemm<1><<<dim3(MODN / 128, MODM / 128), 256, TCG_SMEM>>>(sv, maw, moda, MODM, MODN, DIMC, mab, nullptr);
    tc_gemm<1><<<dim3(MODN / 128, MODM / 128), 256, TCG_SMEM>>>(sv, mfw, modf, MODM, MODN, DIMC, mfb, nullptr);

    // 2) xn = rmsnorm(x) * (1+scale_a) + shift_a
    rmsnorm_mod_k<<<TOT_ROWS, 256>>>(x, n1w, moda, xn);

    // 3) QKV projections
    tc_gemm<0><<<dim3(8, 32), 256, TCG_SMEM>>>(xn, wq, q, TOT_ROWS, DIMC, DIMC, nullptr, nullptr);
    tc_gemm<0><<<dim3(2, 32), 256, TCG_SMEM>>>(xn, wk, k, TOT_ROWS, KVDIM, DIMC, nullptr, nullptr);
    tc_gemm<0><<<dim3(2, 32), 256, TCG_SMEM>>>(xn, wv, v, TOT_ROWS, KVDIM, DIMC, nullptr, nullptr);

    // 4) RoPE
    rope_k<<<(TOT_ROWS * 512 + TOT_ROWS * 128) / 256, 256>>>(q, k, fc, fs);

    // 5) tensor-core block-causal attention
    attn_tc<<<dim3(16, 16, 4), 128, ATT_SMEM>>>(q, k, v, att);

    // 6) h = x + gate_a * (att @ wo^T)
    tc_gemm<2><<<dim3(8, 32), 256, TCG_SMEM>>>(att, wo, h, TOT_ROWS, DIMC, DIMC, x, moda);

    // 7) hn = rmsnorm(h) * (1+scale_f) + shift_f
    rmsnorm_mod_k<<<TOT_ROWS, 256>>>(h, n2w, modf, hn);

    // 8) FFN
    tc_gemm<0><<<dim3(8, 32), 256, TCG_SMEM>>>(hn, w1, u, TOT_ROWS, DIMC, DIMC, nullptr, nullptr);
    tc_gemm<0><<<dim3(8, 32), 256, TCG_SMEM>>>(hn, w3, g, TOT_ROWS, DIMC, DIMC, nullptr, nullptr);
    silumul_k<<<(TOT_ROWS * DIMC) / 256, 256>>>(u, g, f, TOT_ROWS * DIMC);

    // 9) out = h + gate_f * (f @ w2^T)
    tc_gemm<2><<<dim3(8, 32), 256, TCG_SMEM>>>(f, w2, out, TOT_ROWS, DIMC, DIMC, h, modf);
}

// round 16
// speedup vs baseline: 4.4494x; 1.1003x over previous
#include <cuda_runtime.h>
#include <cstdint>
#include <math.h>

// ---------------------------------------------------------------------------
// Problem constants
// ---------------------------------------------------------------------------
#define TOT_ROWS 4096           // B*S
#define DIMC     1024
#define KVDIM    256
#define MODM     512            // B*BLK_NUM
#define MODN     3072

// ---------------- scratch (device globals; no allocations) -----------------
__device__ float g_sv  [MODM * DIMC];
__device__ float g_moda[MODM * MODN];
__device__ float g_modf[MODM * MODN];
__device__ float g_xn  [TOT_ROWS * DIMC];
__device__ float g_q   [TOT_ROWS * DIMC];
__device__ float g_k   [TOT_ROWS * KVDIM];
__device__ float g_v   [TOT_ROWS * KVDIM];
__device__ float g_att [TOT_ROWS * DIMC];
__device__ float g_h   [TOT_ROWS * DIMC];
__device__ float g_hn  [TOT_ROWS * DIMC];
__device__ float g_u   [TOT_ROWS * DIMC];
__device__ float g_f   [TOT_ROWS * DIMC];

// ---------------------------------------------------------------------------
// Helpers (sm_80-baseline PTX: legal on the harness's sm_103 PTX target)
// ---------------------------------------------------------------------------
__device__ __forceinline__ uint32_t smem_u32(const void* p) {
    uint32_t a;
    asm("{ .reg .u64 t; cvta.to.shared.u64 t, %1; cvt.u32.u64 %0, t; }"
        : "=r"(a) : "l"(p));
    return a;
}

__device__ __forceinline__ void cp16(uint32_t dst, const void* src) {
    asm volatile("cp.async.cg.shared.global [%0], [%1], 16;"
                 :: "r"(dst), "l"(src) : "memory");
}
#define CP_COMMIT() asm volatile("cp.async.commit_group;" ::: "memory")
#define CP_WAIT0()  asm volatile("cp.async.wait_group 0;" ::: "memory")

__device__ __forceinline__ uint32_t f2tf32(float f) {
    uint32_t r;
    asm("cvt.rna.tf32.f32 %0, %1;" : "=r"(r) : "f"(f));
    return r;
}

__device__ __forceinline__ void mma_tf32(float* d, const uint32_t* a,
                                         uint32_t b0, uint32_t b1) {
    asm volatile(
        "mma.sync.aligned.m16n8k8.row.col.f32.tf32.tf32.f32 "
        "{%0,%1,%2,%3}, {%4,%5,%6,%7}, {%8,%9}, {%0,%1,%2,%3};"
        : "+f"(d[0]), "+f"(d[1]), "+f"(d[2]), "+f"(d[3])
        : "r"(a[0]), "r"(a[1]), "r"(a[2]), "r"(a[3]), "r"(b0), "r"(b1));
}

__device__ __forceinline__ float silu_f(float v) {
    return v / (1.f + __expf(-v));
}

// ---------------------------------------------------------------------------
// 256x128-tile tf32 GEMM: C[M,N] = A[M,K] * W[N,K]^T  (row-major; W=[N,K])
//   MODE 0: plain
//   MODE 1: + bias; dual-launch: blockIdx.x >= nx1 selects (B2, C2, bias2)
//   MODE 2: C = aux1 + gate*acc, gate[n] = aux2[modrow*3072 + 2048 + n]
//   MODE 3: C = silu(aux1[row,col]) * acc      (FFN w3 + silu-mul fusion)
// 8 warps: 4 along M (64 rows) x 2 along N (64 cols); warp tile 64x64.
// BK=32. SMEM/stage: A 32KB + B 16KB; double buffered = 96KB.
// ---------------------------------------------------------------------------
#define TCG2_SMEM (2 * 49152)

template <int MODE>
__global__ __launch_bounds__(256, 1)
void tc_gemm256(const float* __restrict__ A, const float* __restrict__ B,
                float* __restrict__ C, int M, int N, int K,
                const float* __restrict__ aux1, const float* __restrict__ aux2,
                const float* __restrict__ B2, float* __restrict__ C2,
                const float* __restrict__ bias2, int nx1)
{
    extern __shared__ char smem[];
    const uint32_t sbase = smem_u32(smem);

    const int tid  = threadIdx.x;
    const int wid  = tid >> 5;
    const int lane = tid & 31;
    const int g    = lane >> 2;
    const int t    = lane & 3;
    const int warpM = wid & 3;
    const int warpN = wid >> 2;

    int bx = blockIdx.x;
    const float* Bp = B;
    float* Cp = C;
    const float* biasp = aux1;
    if (MODE == 1 && bx >= nx1) { Bp = B2; Cp = C2; biasp = bias2; bx -= nx1; }
    const int bm = blockIdx.y * 256;
    const int bn = bx * 128;

    float acc[4][8][4];
#pragma unroll
    for (int mi = 0; mi < 4; mi++)
#pragma unroll
        for (int ni = 0; ni < 8; ni++)
#pragma unroll
            for (int r = 0; r < 4; r++) acc[mi][ni][r] = 0.f;

    const int nch = K >> 5;

    auto load_chunk = [&](int ch, int s) {
        const int k0 = ch << 5;
        const uint32_t abase = sbase + s * 49152;
        const uint32_t bbase = abase + 32768;
#pragma unroll
        for (int u = 0; u < 8; u++) {           // A: 256 rows x 8 float4
            const int task = tid + u * 256;
            const int row  = task >> 3;
            const int q    = task & 7;
            const int qs   = q ^ (row & 7);
            cp16(abase + (uint32_t)(row * 8 + qs) * 16,
                 A + (size_t)(bm + row) * K + k0 + q * 4);
        }
#pragma unroll
        for (int u = 0; u < 4; u++) {           // B: 128 rows x 8 float4
            const int task = tid + u * 256;
            const int row  = task >> 3;
            const int q    = task & 7;
            const int qs   = q ^ (row & 7);
            cp16(bbase + (uint32_t)(row * 8 + qs) * 16,
                 Bp + (size_t)(bn + row) * K + k0 + q * 4);
        }
        CP_COMMIT();
    };

    load_chunk(0, 0);
    CP_WAIT0();
    __syncthreads();

    const int sx = g << 2;

    for (int ch = 0; ch < nch; ch++) {
        const int s = ch & 1;
        if (ch + 1 < nch) load_chunk(ch + 1, s ^ 1);

        const float* sA = (const float*)(smem + s * 49152);
        const float* sB = (const float*)(smem + s * 49152 + 32768);

#pragma unroll
        for (int ka = 0; ka < 4; ka++) {
            const int k0 = ka * 8;
            uint32_t a[4][4];
#pragma unroll
            for (int mi = 0; mi < 4; mi++) {
                const int r0 = warpM * 64 + mi * 16 + g;
                a[mi][0] = f2tf32(sA[r0 * 32       + ((k0 + t)     ^ sx)]);
                a[mi][1] = f2tf32(sA[(r0 + 8) * 32 + ((k0 + t)     ^ sx)]);
                a[mi][2] = f2tf32(sA[r0 * 32       + ((k0 + t + 4) ^ sx)]);
                a[mi][3] = f2tf32(sA[(r0 + 8) * 32 + ((k0 + t + 4) ^ sx)]);
            }
#pragma unroll
            for (int ni = 0; ni < 8; ni++) {
                const int c0 = warpN * 64 + ni * 8 + g;
                const uint32_t b0 = f2tf32(sB[c0 * 32 + ((k0 + t)     ^ sx)]);
                const uint32_t b1 = f2tf32(sB[c0 * 32 + ((k0 + t + 4) ^ sx)]);
#pragma unroll
                for (int mi = 0; mi < 4; mi++)
                    mma_tf32(acc[mi][ni], a[mi], b0, b1);
            }
        }

        if (ch + 1 < nch) CP_WAIT0();
        __syncthreads();
    }

#pragma unroll
    for (int mi = 0; mi < 4; mi++) {
#pragma unroll
        for (int ni = 0; ni < 8; ni++) {
            const int row0 = bm + warpM * 64 + mi * 16 + g;
            const int row1 = row0 + 8;
            const int col  = bn + warpN * 64 + ni * 8 + t * 2;
            float2 v0 = make_float2(acc[mi][ni][0], acc[mi][ni][1]);
            float2 v1 = make_float2(acc[mi][ni][2], acc[mi][ni][3]);
            if (MODE == 0) {
                *(float2*)(Cp + (size_t)row0 * N + col) = v0;
                *(float2*)(Cp + (size_t)row1 * N + col) = v1;
            } else if (MODE == 1) {
                const float2 bi = *(const float2*)(biasp + col);
                v0.x += bi.x; v0.y += bi.y;
                v1.x += bi.x; v1.y += bi.y;
                *(float2*)(Cp + (size_t)row0 * N + col) = v0;
                *(float2*)(Cp + (size_t)row1 * N + col) = v1;
            } else if (MODE == 2) {
                const int mr0 = ((row0 >> 10) << 7) + ((row0 & 1023) >> 3);
                const int mr1 = ((row1 >> 10) << 7) + ((row1 & 1023) >> 3);
                const float2 gt0 = *(const float2*)(aux2 + (size_t)mr0 * MODN + 2048 + col);
                const float2 gt1 = *(const float2*)(aux2 + (size_t)mr1 * MODN + 2048 + col);
                const float2 rs0 = *(const float2*)(aux1 + (size_t)row0 * N + col);
                const float2 rs1 = *(const float2*)(aux1 + (size_t)row1 * N + col);
                v0.x = rs0.x + gt0.x * v0.x; v0.y = rs0.y + gt0.y * v0.y;
                v1.x = rs1.x + gt1.x * v1.x; v1.y = rs1.y + gt1.y * v1.y;
                *(float2*)(Cp + (size_t)row0 * N + col) = v0;
                *(float2*)(Cp + (size_t)row1 * N + col) = v1;
            } else {  // MODE 3: silu(u) * acc
                const float2 u0 = *(const float2*)(aux1 + (size_t)row0 * N + col);
                const float2 u1 = *(const float2*)(aux1 + (size_t)row1 * N + col);
                v0.x *= silu_f(u0.x); v0.y *= silu_f(u0.y);
                v1.x *= silu_f(u1.x); v1.y *= silu_f(u1.y);
                *(float2*)(Cp + (size_t)row0 * N + col) = v0;
                *(float2*)(Cp + (size_t)row1 * N + col) = v1;
            }
        }
    }
}

// ---------------------------------------------------------------------------
// Fused QKV projection + RoPE (128x128 tiles, K=1024 fixed).
// grid.x = 12: [0,8) -> q cols, [8,10) -> k cols, [10,12) -> v cols.
// RoPE fused in epilogue: each thread's fragment pair (col, col+1) with col
// even is exactly one rotation pair; i = (col & 63) >> 1, s = row & 1023.
// ---------------------------------------------------------------------------
#define TCG_SMEM (2 * 32768)

__global__ __launch_bounds__(256, 2)
void tc_qkv(const float* __restrict__ A,
            const float* __restrict__ Wq, const float* __restrict__ Wk,
            const float* __restrict__ Wv,
            float* __restrict__ Oq, float* __restrict__ Ok, float* __restrict__ Ov,
            const float* __restrict__ fc, const float* __restrict__ fs)
{
    extern __shared__ char smem[];
    const uint32_t sbase = smem_u32(smem);

    const int tid  = threadIdx.x;
    const int wid  = tid >> 5;
    const int lane = tid & 31;
    const int g    = lane >> 2;
    const int t    = lane & 3;
    const int warpM = wid & 3;
    const int warpN = wid >> 2;
    const int bm = blockIdx.y * 128;

    const int bx = blockIdx.x;
    const float* W;
    float* C;
    int Nout, bn;
    bool dorope;
    if (bx < 8)       { W = Wq; C = Oq; Nout = DIMC;  bn = bx * 128;        dorope = true;  }
    else if (bx < 10) { W = Wk; C = Ok; Nout = KVDIM; bn = (bx - 8) * 128;  dorope = true;  }
    else              { W = Wv; C = Ov; Nout = KVDIM; bn = (bx - 10) * 128; dorope = false; }

    float acc[2][8][4];
#pragma unroll
    for (int mi = 0; mi < 2; mi++)
#pragma unroll
        for (int ni = 0; ni < 8; ni++)
#pragma unroll
            for (int r = 0; r < 4; r++) acc[mi][ni][r] = 0.f;

    auto load_chunk = [&](int ch, int s) {
        const int k0 = ch << 5;
        const uint32_t abase = sbase + s * 32768;
        const uint32_t bbase = abase + 16384;
#pragma unroll
        for (int u = 0; u < 4; u++) {
            const int task = tid + u * 256;
            const int row  = task >> 3;
            const int q    = task & 7;
            const int qs   = q ^ (row & 7);
            const uint32_t off = (uint32_t)(row * 8 + qs) * 16;
            cp16(abase + off, A + (size_t)(bm + row) * DIMC + k0 + q * 4);
            cp16(bbase + off, W + (size_t)(bn + row) * DIMC + k0 + q * 4);
        }
        CP_COMMIT();
    };

    load_chunk(0, 0);
    CP_WAIT0();
    __syncthreads();

    const int sx = g << 2;

    for (int ch = 0; ch < 32; ch++) {
        const int s = ch & 1;
        if (ch + 1 < 32) load_chunk(ch + 1, s ^ 1);

        const float* sA = (const float*)(smem + s * 32768);
        const float* sB = (const float*)(smem + s * 32768 + 16384);

#pragma unroll
        for (int ka = 0; ka < 4; ka++) {
            const int k0 = ka * 8;
            uint32_t a[2][4];
#pragma unroll
            for (int mi = 0; mi < 2; mi++) {
                const int r0 = warpM * 32 + mi * 16 + g;
                a[mi][0] = f2tf32(sA[r0 * 32       + ((k0 + t)     ^ sx)]);
                a[mi][1] = f2tf32(sA[(r0 + 8) * 32 + ((k0 + t)     ^ sx)]);
                a[mi][2] = f2tf32(sA[r0 * 32       + ((k0 + t + 4) ^ sx)]);
                a[mi][3] = f2tf32(sA[(r0 + 8) * 32 + ((k0 + t + 4) ^ sx)]);
            }
#pragma unroll
            for (int ni = 0; ni < 8; ni++) {
                const int c0 = warpN * 64 + ni * 8 + g;
                const uint32_t b0 = f2tf32(sB[c0 * 32 + ((k0 + t)     ^ sx)]);
                const uint32_t b1 = f2tf32(sB[c0 * 32 + ((k0 + t + 4) ^ sx)]);
                mma_tf32(acc[0][ni], a[0], b0, b1);
                mma_tf32(acc[1][ni], a[1], b0, b1);
            }
        }

        if (ch + 1 < 32) CP_WAIT0();
        __syncthreads();
    }

#pragma unroll
    for (int mi = 0; mi < 2; mi++) {
#pragma unroll
        for (int ni = 0; ni < 8; ni++) {
            const int row0 = bm + warpM * 32 + mi * 16 + g;
            const int row1 = row0 + 8;
            const int col  = bn + warpN * 64 + ni * 8 + t * 2;
            float2 v0 = make_float2(acc[mi][ni][0], acc[mi][ni][1]);
            float2 v1 = make_float2(acc[mi][ni][2], acc[mi][ni][3]);
            if (dorope) {
                const int i  = (col & 63) >> 1;
                const int s0 = row0 & 1023;
                const int s1 = row1 & 1023;
                const float c0r = fc[s0 * 32 + i], s0r = fs[s0 * 32 + i];
                const float c1r = fc[s1 * 32 + i], s1r = fs[s1 * 32 + i];
                v0 = make_float2(v0.x * c0r - v0.y * s0r, v0.x * s0r + v0.y * c0r);
                v1 = make_float2(v1.x * c1r - v1.y * s1r, v1.x * s1r + v1.y * c1r);
            }
            *(float2*)(C + (size_t)row0 * Nout + col) = v0;
            *(float2*)(C + (size_t)row1 * Nout + col) = v1;
        }
    }
}

// ---------------------------------------------------------------------------
// Tensor-core block-causal flash attention (unchanged; validated R15).
// ---------------------------------------------------------------------------
#define KST 68
#define VST 72
#define ATT_SMEM ((2 * 64 * KST + 2 * 64 * VST + 4 * 16 * KST) * 4)

__global__ __launch_bounds__(128, 2)
void attn_tc(const float* __restrict__ Q, const float* __restrict__ K,
             const float* __restrict__ V, float* __restrict__ O)
{
    extern __shared__ float sm[];
    const uint32_t sbase = smem_u32(sm);

    const int qt = blockIdx.x, h = blockIdx.y, b = blockIdx.z;
    const int kvh = h >> 2;
    const int tid = threadIdx.x;
    const int wid = tid >> 5;
    const int lane = tid & 31;
    const int g = lane >> 2;
    const int t = lane & 3;

    const int K0 = 0, K1 = 64 * KST;
    const int V0 = 2 * 64 * KST, V1 = V0 + 64 * VST;
    float* sP = sm + 2 * 64 * KST + 2 * 64 * VST + wid * (16 * KST);

    const float* qb = Q + (size_t)(b * 1024 + qt * 64 + wid * 16) * DIMC + h * 64;
    uint32_t qa[8][4];
#pragma unroll
    for (int ka = 0; ka < 8; ka++) {
        const int c = ka * 8;
        qa[ka][0] = f2tf32(0.125f * qb[(size_t)g * DIMC + c + t]);
        qa[ka][1] = f2tf32(0.125f * qb[(size_t)(g + 8) * DIMC + c + t]);
        qa[ka][2] = f2tf32(0.125f * qb[(size_t)g * DIMC + c + t + 4]);
        qa[ka][3] = f2tf32(0.125f * qb[(size_t)(g + 8) * DIMC + c + t + 4]);
    }

    float oacc[8][4];
#pragma unroll
    for (int na = 0; na < 8; na++)
#pragma unroll
        for (int r = 0; r < 4; r++) oacc[na][r] = 0.f;
    float m0 = -1e30f, m1 = -1e30f, l0 = 0.f, l1 = 0.f;

    auto load_kv = [&](int kc, int s) {
        const float* kb = K + (size_t)(b * 1024 + kc * 64) * KVDIM + kvh * 64;
        const float* vb = V + (size_t)(b * 1024 + kc * 64) * KVDIM + kvh * 64;
        const uint32_t kst = sbase + (s ? K1 : K0) * 4;
        const uint32_t vst = sbase + (s ? V1 : V0) * 4;
#pragma unroll
        for (int u = 0; u < 8; u++) {
            const int task = tid + u * 128;
            const int row  = task >> 4;
            const int q4   = task & 15;
            cp16(kst + (uint32_t)(row * KST + q4 * 4) * 4, kb + (size_t)row * KVDIM + q4 * 4);
            cp16(vst + (uint32_t)(row * VST + q4 * 4) * 4, vb + (size_t)row * KVDIM + q4 * 4);
        }
        CP_COMMIT();
    };

    load_kv(0, 0);
    CP_WAIT0();
    __syncthreads();

    for (int kc = 0; kc <= qt; kc++) {
        const int s = kc & 1;
        if (kc < qt) load_kv(kc + 1, s ^ 1);

        const float* sK = sm + (s ? K1 : K0);
        const float* sV = sm + (s ? V1 : V0);

        float sacc[8][4];
#pragma unroll
        for (int na = 0; na < 8; na++)
#pragma unroll
            for (int r = 0; r < 4; r++) sacc[na][r] = 0.f;

#pragma unroll
        for (int ka = 0; ka < 8; ka++) {
            const int k0 = ka * 8;
#pragma unroll
            for (int na = 0; na < 8; na++) {
                const int n0 = na * 8 + g;
                const uint32_t b0 = f2tf32(sK[n0 * KST + k0 + t]);
                const uint32_t b1 = f2tf32(sK[n0 * KST + k0 + t + 4]);
                mma_tf32(sacc[na], qa[ka], b0, b1);
            }
        }

        if (kc == qt) {
            const int rb0 = wid * 2;
            const int rb1 = rb0 + 1;
#pragma unroll
            for (int na = 0; na < 8; na++) {
                if (na > rb0) { sacc[na][0] = -1e30f; sacc[na][1] = -1e30f; }
                if (na > rb1) { sacc[na][2] = -1e30f; sacc[na][3] = -1e30f; }
            }
        }

        float mx0 = -1e30f, mx1 = -1e30f;
#pragma unroll
        for (int na = 0; na < 8; na++) {
            mx0 = fmaxf(mx0, fmaxf(sacc[na][0], sacc[na][1]));
            mx1 = fmaxf(mx1, fmaxf(sacc[na][2], sacc[na][3]));
        }
        mx0 = fmaxf(mx0, __shfl_xor_sync(0xffffffffu, mx0, 1));
        mx0 = fmaxf(mx0, __shfl_xor_sync(0xffffffffu, mx0, 2));
        mx1 = fmaxf(mx1, __shfl_xor_sync(0xffffffffu, mx1, 1));
        mx1 = fmaxf(mx1, __shfl_xor_sync(0xffffffffu, mx1, 2));

        const float mn0 = fmaxf(m0, mx0);
        const float mn1 = fmaxf(m1, mx1);
        const float c0 = __expf(m0 - mn0);
        const float c1 = __expf(m1 - mn1);
        l0 *= c0; l1 *= c1;
#pragma unroll
        for (int na = 0; na < 8; na++) {
            oacc[na][0] *= c0; oacc[na][1] *= c0;
            oacc[na][2] *= c1; oacc[na][3] *= c1;
        }
#pragma unroll
        for (int na = 0; na < 8; na++) {
            const float p0 = __expf(sacc[na][0] - mn0);
            const float p1 = __expf(sacc[na][1] - mn0);
            const float p2 = __expf(sacc[na][2] - mn1);
            const float p3 = __expf(sacc[na][3] - mn1);
            l0 += p0 + p1;
            l1 += p2 + p3;
            sP[g * KST + na * 8 + 2 * t]           = p0;
            sP[g * KST + na * 8 + 2 * t + 1]       = p1;
            sP[(g + 8) * KST + na * 8 + 2 * t]     = p2;
            sP[(g + 8) * KST + na * 8 + 2 * t + 1] = p3;
        }
        m0 = mn0; m1 = mn1;
        __syncwarp();

#pragma unroll
        for (int ka = 0; ka < 8; ka++) {
            uint32_t pa[4];
            pa[0] = f2tf32(sP[g * KST + ka * 8 + t]);
            pa[1] = f2tf32(sP[(g + 8) * KST + ka * 8 + t]);
            pa[2] = f2tf32(sP[g * KST + ka * 8 + t + 4]);
            pa[3] = f2tf32(sP[(g + 8) * KST + ka * 8 + t + 4]);
#pragma unroll
            for (int na = 0; na < 8; na++) {
                const uint32_t b0 = f2tf32(sV[(ka * 8 + t) * VST + na * 8 + g]);
                const uint32_t b1 = f2tf32(sV[(ka * 8 + t + 4) * VST + na * 8 + g]);
                mma_tf32(oacc[na], pa, b0, b1);
            }
        }
        __syncwarp();

        if (kc < qt) CP_WAIT0();
        __syncthreads();
    }

    l0 += __shfl_xor_sync(0xffffffffu, l0, 1);
    l0 += __shfl_xor_sync(0xffffffffu, l0, 2);
    l1 += __shfl_xor_sync(0xffffffffu, l1, 1);
    l1 += __shfl_xor_sync(0xffffffffu, l1, 2);
    const float i0 = 1.f / l0;
    const float i1 = 1.f / l1;

    const size_t r0 = (size_t)(b * 1024 + qt * 64 + wid * 16 + g);
    const size_t r1 = r0 + 8;
#pragma unroll
    for (int na = 0; na < 8; na++) {
        const int col = h * 64 + na * 8 + 2 * t;
        *(float2*)(O + r0 * DIMC + col) = make_float2(oacc[na][0] * i0, oacc[na][1] * i0);
        *(float2*)(O + r1 * DIMC + col) = make_float2(oacc[na][2] * i1, oacc[na][3] * i1);
    }
}

// ---------------------------------------------------------------------------
// silu elementwise
// ---------------------------------------------------------------------------
__global__ void silu_k(const float* __restrict__ in, float* __restrict__ out, int n)
{
    int i = blockIdx.x * blockDim.x + threadIdx.x;
    if (i < n) {
        float v = in[i];
        out[i] = v / (1.f + __expf(-v));
    }
}

// ---------------------------------------------------------------------------
// Fused rmsnorm + adaLN modulation
// ---------------------------------------------------------------------------
__global__ __launch_bounds__(256)
void rmsnorm_mod_k(const float* __restrict__ X, const float* __restrict__ w,
                   const float* __restrict__ mod, float* __restrict__ Y)
{
    const int row = blockIdx.x;
    const int modrow = ((row >> 10) << 7) + ((row & 1023) >> 3);
    const float* x  = X + (size_t)row * DIMC;
    const float* sh = mod + (size_t)modrow * MODN;
    const float* sc = sh + 1024;
    const int t = threadIdx.x;

    float4 xv = *(const float4*)(x + t * 4);
    float ss = xv.x * xv.x + xv.y * xv.y + xv.z * xv.z + xv.w * xv.w;
#pragma unroll
    for (int o = 16; o > 0; o >>= 1) ss += __shfl_xor_sync(0xffffffffu, ss, o);

    __shared__ float red[8];
    if ((t & 31) == 0) red[t >> 5] = ss;
    __syncthreads();
    float tot = 0.f;
#pragma unroll
    for (int i = 0; i < 8; i++) tot += red[i];

    float rinv = rsqrtf(tot * (1.f / 1024.f) + 1e-6f);
    float4 wv = *(const float4*)(w + t * 4);
    float4 scv = *(const float4*)(sc + t * 4);
    float4 shv = *(const float4*)(sh + t * 4);
    float4 yv;
    yv.x = xv.x * rinv * wv.x * (1.f + scv.x) + shv.x;
    yv.y = xv.y * rinv * wv.y * (1.f + scv.y) + shv.y;
    yv.z = xv.z * rinv * wv.z * (1.f + scv.z) + shv.z;
    yv.w = xv.w * rinv * wv.w * (1.f + scv.w) + shv.w;
    *(float4*)(Y + (size_t)row * DIMC + t * 4) = yv;
}

// ---------------------------------------------------------------------------
// Launcher
// ---------------------------------------------------------------------------
extern "C" void kernel_launch(void* const* d_in, const int* in_sizes, int n_in,
                              void* d_out, int out_size)
{
    (void)in_sizes; (void)n_in; (void)out_size;
    const float* x   = (const float*)d_in[0];
    const float* vec = (const float*)d_in[1];
    const float* wq  = (const float*)d_in[2];
    const float* wk  = (const float*)d_in[3];
    const float* wv  = (const float*)d_in[4];
    const float* wo  = (const float*)d_in[5];
    const float* w1  = (const float*)d_in[6];
    const float* w2  = (const float*)d_in[7];
    const float* w3  = (const float*)d_in[8];
    const float* maw = (const float*)d_in[9];
    const float* mab = (const float*)d_in[10];
    const float* mfw = (const float*)d_in[11];
    const float* mfb = (const float*)d_in[12];
    const float* n1w = (const float*)d_in[13];
    const float* n2w = (const float*)d_in[14];
    const float* fc  = (const float*)d_in[15];
    const float* fs  = (const float*)d_in[16];
    float* out = (float*)d_out;

    float *sv, *moda, *modf, *xn, *q, *k, *v, *att, *h, *hn, *u, *f;
    cudaGetSymbolAddress((void**)&sv,   g_sv);
    cudaGetSymbolAddress((void**)&moda, g_moda);
    cudaGetSymbolAddress((void**)&modf, g_modf);
    cudaGetSymbolAddress((void**)&xn,   g_xn);
    cudaGetSymbolAddress((void**)&q,    g_q);
    cudaGetSymbolAddress((void**)&k,    g_k);
    cudaGetSymbolAddress((void**)&v,    g_v);
    cudaGetSymbolAddress((void**)&att,  g_att);
    cudaGetSymbolAddress((void**)&h,    g_h);
    cudaGetSymbolAddress((void**)&hn,   g_hn);
    cudaGetSymbolAddress((void**)&u,    g_u);
    cudaGetSymbolAddress((void**)&f,    g_f);

    cudaFuncSetAttribute(tc_gemm256<0>, cudaFuncAttributeMaxDynamicSharedMemorySize, TCG2_SMEM);
    cudaFuncSetAttribute(tc_gemm256<1>, cudaFuncAttributeMaxDynamicSharedMemorySize, TCG2_SMEM);
    cudaFuncSetAttribute(tc_gemm256<2>, cudaFuncAttributeMaxDynamicSharedMemorySize, TCG2_SMEM);
    cudaFuncSetAttribute(tc_gemm256<3>, cudaFuncAttributeMaxDynamicSharedMemorySize, TCG2_SMEM);
    cudaFuncSetAttribute(tc_qkv,        cudaFuncAttributeMaxDynamicSharedMemorySize, TCG_SMEM);
    cudaFuncSetAttribute(attn_tc,       cudaFuncAttributeMaxDynamicSharedMemorySize, ATT_SMEM);

    // 1) modulation: silu(vec), then BOTH (512,3072,1024) GEMMs in one launch
    silu_k<<<(MODM * DIMC) / 256, 256>>>(vec, sv, MODM * DIMC);
    tc_gemm256<1><<<dim3(48, 2), 256, TCG2_SMEM>>>(sv, maw, moda, MODM, MODN, DIMC,
                                                   mab, nullptr, mfw, modf, mfb, 24);

    // 2) xn = rmsnorm(x) * (1+scale_a) + shift_a
    rmsnorm_mod_k<<<TOT_ROWS, 256>>>(x, n1w, moda, xn);

    // 3) fused QKV projection + RoPE (single launch)
    tc_qkv<<<dim3(12, 32), 256, TCG_SMEM>>>(xn, wq, wk, wv, q, k, v, fc, fs);

    // 4) tensor-core block-causal attention
    attn_tc<<<dim3(16, 16, 4), 128, ATT_SMEM>>>(q, k, v, att);

    // 5) h = x + gate_a * (att @ wo^T)
    tc_gemm256<2><<<dim3(8, 16), 256, TCG2_SMEM>>>(att, wo, h, TOT_ROWS, DIMC, DIMC,
                                                   x, moda, nullptr, nullptr, nullptr, 0);

    // 6) hn = rmsnorm(h) * (1+scale_f) + shift_f
    rmsnorm_mod_k<<<TOT_ROWS, 256>>>(h, n2w, modf, hn);

    // 7) FFN: u = hn w1^T; f = silu(u) * (hn w3^T)  (silu-mul fused in w3)
    tc_gemm256<0><<<dim3(8, 16), 256, TCG2_SMEM>>>(hn, w1, u, TOT_ROWS, DIMC, DIMC,
                                                   nullptr, nullptr, nullptr, nullptr, nullptr, 0);
    tc_gemm256<3><<<dim3(8, 16), 256, TCG2_SMEM>>>(hn, w3, f, TOT_ROWS, DIMC, DIMC,
                                                   u, nullptr, nullptr, nullptr, nullptr, 0);

    // 8) out = h + gate_f * (f @ w2^T)
    tc_gemm256<2><<<dim3(8, 16), 256, TCG2_SMEM>>>(f, w2, out, TOT_ROWS, DIMC, DIMC,
                                                   h, modf, nullptr, nullptr, nullptr, 0);
}